// round 1
// baseline (speedup 1.0000x reference)
#include <cuda_runtime.h>

#define LOG2E 1.4426950408889634f

// ---------------- scratch (device globals; no allocation allowed) -------------
__device__ float g_k[32 * 2 * 2048];     // [c][b][n]
__device__ float g_q[32 * 2048 * 2];     // [c][n][b]
__device__ float g_v[32 * 2048 * 2];     // [c][n][b]
__device__ float g_vz[32 * 2048 * 2];    // v * (1/Z) per column
__device__ float g_nm[32 * 2048];        // -(max logit)*log2e per (c,m)
__device__ float g_attn[32 * 2048 * 2];  // flat [C,N,B] attention output

// =============================================================================
// Kernel A: fused conv3d for key/query/value (64 -> 3x32 channels, 3x3x3, pad 1)
// grid (cog=8, d=8, b=2), 192 threads = 12 co x 16 h, each thread does a W-row.
// =============================================================================
__global__ __launch_bounds__(192) void conv_qkv_kernel(
    const float* __restrict__ x,
    const float* __restrict__ wk, const float* __restrict__ bk,
    const float* __restrict__ wq, const float* __restrict__ bq,
    const float* __restrict__ wv, const float* __restrict__ bv)
{
    __shared__ float tile[3 * 18 * 18];   // one input channel, d/h/w halo, zero-padded
    const int t   = threadIdx.x;
    const int b   = blockIdx.z;
    const int d   = blockIdx.y;
    const int cog = blockIdx.x;
    const int co  = cog * 12 + (t >> 4);  // 0..95
    const int h   = t & 15;
    const int which = co >> 5;            // 0=key 1=query 2=value
    const int c     = co & 31;

    const float* W  = (which == 0) ? wk : (which == 1 ? wq : wv);
    const float* Bs = (which == 0) ? bk : (which == 1 ? bq : bv);

    float acc[16];
    {
        const float bias = Bs[c];
        #pragma unroll
        for (int w = 0; w < 16; w++) acc[w] = bias;
    }
    const float* Wc = W + c * 64 * 27;

    for (int ci = 0; ci < 64; ci++) {
        __syncthreads();
        for (int i = t; i < 972; i += 192) {
            int dd = i / 324, r = i % 324, hh = r / 18, ww = r % 18;
            int gd = d + dd - 1, gh = hh - 1, gw = ww - 1;
            float val = 0.f;
            if ((unsigned)gd < 8u && (unsigned)gh < 16u && (unsigned)gw < 16u)
                val = x[(((b * 64 + ci) * 8 + gd) * 16 + gh) * 16 + gw];
            tile[i] = val;
        }
        __syncthreads();
        const float* Wci = Wc + ci * 27;
        #pragma unroll
        for (int kd = 0; kd < 3; kd++) {
            #pragma unroll
            for (int kh = 0; kh < 3; kh++) {
                const float* row = &tile[(kd * 18 + h + kh) * 18];
                float r0[18];
                #pragma unroll
                for (int j = 0; j < 18; j++) r0[j] = row[j];
                const float w0 = Wci[(kd * 3 + kh) * 3 + 0];
                const float w1 = Wci[(kd * 3 + kh) * 3 + 1];
                const float w2 = Wci[(kd * 3 + kh) * 3 + 2];
                #pragma unroll
                for (int w = 0; w < 16; w++)
                    acc[w] = fmaf(w0, r0[w], fmaf(w1, r0[w + 1], fmaf(w2, r0[w + 2], acc[w])));
            }
        }
    }

    const int nbase = d * 256 + h * 16;
    if (which == 0) {
        #pragma unroll
        for (int w = 0; w < 16; w++)
            g_k[(c * 2 + b) * 2048 + nbase + w] = acc[w];
    } else {
        float* dst = (which == 1) ? g_q : g_v;
        #pragma unroll
        for (int w = 0; w < 16; w++)
            dst[(c * 2048 + nbase + w) * 2 + b] = acc[w];
    }
}

// =============================================================================
// Kernel B: per-column softmax stats. softmax is over the ROW axis n (axis=1),
// i.e. normalized per column m. Rank-2 logits: s = q(n).k(m), dim 2.
// Works in log2 domain. Also folds 1/Z into V.
// grid (mchunk=8, c=32), 256 threads, 1 column per thread.
// =============================================================================
__global__ __launch_bounds__(256) void colstats_kernel()
{
    __shared__ float2 sq[2048];   // q[c][n][0..1]
    const int t = threadIdx.x;
    const int c = blockIdx.y;
    const int m = blockIdx.x * 256 + t;

    const float2* qsrc = (const float2*)(g_q + c * 4096);
    for (int i = t; i < 2048; i += 256) sq[i] = qsrc[i];
    __syncthreads();

    const float k0 = g_k[(c * 2 + 0) * 2048 + m] * LOG2E;
    const float k1 = g_k[(c * 2 + 1) * 2048 + m] * LOG2E;

    float M = -1e30f;
    #pragma unroll 8
    for (int n = 0; n < 2048; n++) {
        float2 q = sq[n];
        float s = fmaf(q.x, k0, q.y * k1);
        M = fmaxf(M, s);
    }
    float Z = 0.f;
    #pragma unroll 4
    for (int n = 0; n < 2048; n++) {
        float2 q = sq[n];
        float s = fmaf(q.x, k0, fmaf(q.y, k1, -M));
        float e;
        asm("ex2.approx.ftz.f32 %0, %1;" : "=f"(e) : "f"(s));
        Z += e;
    }
    const float invZ = 1.f / Z;
    g_nm[c * 2048 + m] = -M;
    g_vz[(c * 2048 + m) * 2 + 0] = g_v[(c * 2048 + m) * 2 + 0] * invZ;
    g_vz[(c * 2048 + m) * 2 + 1] = g_v[(c * 2048 + m) * 2 + 1] * invZ;
}

// =============================================================================
// Kernel C: out[c,n,b] = sum_m 2^(s2[n,m] - M2[m]) * vz[m,b]
// grid (nchunk=8, c=32), 256 threads, 1 row per thread.
// Inner loop: LDS.128 + LDS.64 + 2 FFMA + EX2 + 2 FFMA.
// =============================================================================
__global__ __launch_bounds__(256) void attn_out_kernel()
{
    __shared__ float4 ksm[2048];  // (k0*log2e, k1*log2e, -M2, pad)  32KB
    __shared__ float2 vzs[2048];  //                                 16KB
    const int t = threadIdx.x;
    const int c = blockIdx.y;
    const int n = blockIdx.x * 256 + t;

    for (int i = t; i < 2048; i += 256) {
        ksm[i] = make_float4(g_k[(c * 2 + 0) * 2048 + i] * LOG2E,
                             g_k[(c * 2 + 1) * 2048 + i] * LOG2E,
                             g_nm[c * 2048 + i], 0.f);
        vzs[i] = ((const float2*)(g_vz + c * 4096))[i];
    }
    __syncthreads();

    const float2 qn = ((const float2*)(g_q + c * 4096))[n];
    float a0 = 0.f, a1 = 0.f;
    #pragma unroll 4
    for (int m = 0; m < 2048; m++) {
        float4 kk = ksm[m];
        float s = fmaf(qn.x, kk.x, fmaf(qn.y, kk.y, kk.z));
        float e;
        asm("ex2.approx.ftz.f32 %0, %1;" : "=f"(e) : "f"(s));
        float2 vv = vzs[m];
        a0 = fmaf(e, vv.x, a0);
        a1 = fmaf(e, vv.y, a1);
    }
    ((float2*)(g_attn + c * 4096))[n] = make_float2(a0, a1);
}

// =============================================================================
// Kernel D: conv_alter (32 -> 64, 3x3x3, pad 1) + bias + residual.
// Input is g_attn flat [C,N,B] REINTERPRETED as [B,32,D,H,W] (the torch .view):
// element (b,ci,n) lives at flat index (b*32+ci)*2048 + n.
// grid (cog=8, d=8, b=2), 128 threads = 8 co x 16 h.
// =============================================================================
__global__ __launch_bounds__(128) void conv_alter_kernel(
    const float* __restrict__ x,
    const float* __restrict__ wa, const float* __restrict__ ba,
    float* __restrict__ out)
{
    __shared__ float tile[3 * 18 * 18];
    const int t   = threadIdx.x;
    const int b   = blockIdx.z;
    const int d   = blockIdx.y;
    const int cog = blockIdx.x;
    const int co  = cog * 8 + (t >> 4);   // 0..63
    const int h   = t & 15;

    float acc[16];
    {
        const float bias = ba[co];
        #pragma unroll
        for (int w = 0; w < 16; w++) acc[w] = bias;
    }
    const float* Wc = wa + co * 32 * 27;

    for (int ci = 0; ci < 32; ci++) {
        __syncthreads();
        for (int i = t; i < 972; i += 128) {
            int dd = i / 324, r = i % 324, hh = r / 18, ww = r % 18;
            int gd = d + dd - 1, gh = hh - 1, gw = ww - 1;
            float val = 0.f;
            if ((unsigned)gd < 8u && (unsigned)gh < 16u && (unsigned)gw < 16u)
                val = g_attn[(b * 32 + ci) * 2048 + gd * 256 + gh * 16 + gw];
            tile[i] = val;
        }
        __syncthreads();
        const float* Wci = Wc + ci * 27;
        #pragma unroll
        for (int kd = 0; kd < 3; kd++) {
            #pragma unroll
            for (int kh = 0; kh < 3; kh++) {
                const float* row = &tile[(kd * 18 + h + kh) * 18];
                float r0[18];
                #pragma unroll
                for (int j = 0; j < 18; j++) r0[j] = row[j];
                const float w0 = Wci[(kd * 3 + kh) * 3 + 0];
                const float w1 = Wci[(kd * 3 + kh) * 3 + 1];
                const float w2 = Wci[(kd * 3 + kh) * 3 + 2];
                #pragma unroll
                for (int w = 0; w < 16; w++)
                    acc[w] = fmaf(w0, r0[w], fmaf(w1, r0[w + 1], fmaf(w2, r0[w + 2], acc[w])));
            }
        }
    }

    const int nbase = d * 256 + h * 16;
    #pragma unroll
    for (int w = 0; w < 16; w++) {
        const int idx = (b * 64 + co) * 2048 + nbase + w;
        out[idx] = x[idx] + acc[w];
    }
}

// =============================================================================
extern "C" void kernel_launch(void* const* d_in, const int* in_sizes, int n_in,
                              void* d_out, int out_size)
{
    const float* x  = (const float*)d_in[0];
    const float* wk = (const float*)d_in[1];
    const float* bk = (const float*)d_in[2];
    const float* wq = (const float*)d_in[3];
    const float* bq = (const float*)d_in[4];
    const float* wv = (const float*)d_in[5];
    const float* bv = (const float*)d_in[6];
    const float* wa = (const float*)d_in[7];
    const float* ba = (const float*)d_in[8];
    float* out = (float*)d_out;

    conv_qkv_kernel<<<dim3(8, 8, 2), 192>>>(x, wk, bk, wq, bq, wv, bv);
    colstats_kernel<<<dim3(8, 32), 256>>>();
    attn_out_kernel<<<dim3(8, 32), 256>>>();
    conv_alter_kernel<<<dim3(8, 8, 2), 128>>>(x, wa, ba, out);
}